// round 7
// baseline (speedup 1.0000x reference)
#include <cuda_runtime.h>
#include <cuda_fp16.h>
#include <math.h>
#include <stdint.h>

#define B 8
#define N 1024
#define H 16
#define D 64
#define HD 1024

// Scratch (allocation-free): fp16 Q/K, fp16 V transposed [b][h][d][n], fp32 bias
__device__ __half g_Qh[B * H * N * D];
__device__ __half g_Kh[B * H * N * D];
__device__ __half g_Vt[B * H * D * N];
__device__ float  g_RB[H * N * N];

__device__ __forceinline__ uint32_t f2h2(float lo, float hi) {
    __half2 h = __floats2half2_rn(lo, hi);
    return *(uint32_t*)&h;
}

__device__ __forceinline__ void mma16(float* d, const uint32_t* a, const uint32_t* b) {
    asm volatile(
        "mma.sync.aligned.m16n8k16.row.col.f32.f16.f16.f32 "
        "{%0,%1,%2,%3}, {%4,%5,%6,%7}, {%8,%9}, {%0,%1,%2,%3};"
        : "+f"(d[0]), "+f"(d[1]), "+f"(d[2]), "+f"(d[3])
        : "r"(a[0]), "r"(a[1]), "r"(a[2]), "r"(a[3]), "r"(b[0]), "r"(b[1]));
}

__device__ __forceinline__ void ldm4(uint32_t* d, uint32_t a) {
    asm volatile("ldmatrix.sync.aligned.m8n8.x4.shared.b16 {%0,%1,%2,%3}, [%4];"
        : "=r"(d[0]), "=r"(d[1]), "=r"(d[2]), "=r"(d[3]) : "r"(a));
}

#define STS64V(addr, u) asm volatile("st.shared.v2.b32 [%0], {%1,%2};" \
    :: "r"(addr), "r"((u).x), "r"((u).y) : "memory")
#define STS128V(addr, u) asm volatile("st.shared.v4.b32 [%0], {%1,%2,%3,%4};" \
    :: "r"(addr), "r"((u).x), "r"((u).y), "r"((u).z), "r"((u).w) : "memory")

__device__ __forceinline__ uint32_t smem_u32(const void* p) {
    uint32_t a;
    asm("{ .reg .u64 t; cvta.to.shared.u64 t, %1; cvt.u32.u64 %0, t; }"
        : "=r"(a) : "l"(p));
    return a;
}

// ---------------------------------------------------------------------------
// Kernel 0: combined bias = rel_pos + rel_2d_pos
// ---------------------------------------------------------------------------
__global__ __launch_bounds__(256) void bias_kernel(
    const float* __restrict__ rel, const float* __restrict__ rel2)
{
    size_t i = ((size_t)blockIdx.x * 256 + threadIdx.x) * 4;
    float4 a = *(const float4*)&rel[i];
    float4 b = *(const float4*)&rel2[i];
    a.x += b.x; a.y += b.y; a.z += b.z; a.w += b.w;
    *(float4*)&g_RB[i] = a;
}

// ---------------------------------------------------------------------------
// Kernel 1: QKV projection, fp16 m16n8k16 + ldmatrix fragment loads.
// CTA 128(o) x 256(tok), 8 warps, warp tile 64x64, BK=16 double-buffered.
// pitch 12 words (48B: stride/16=3 odd -> ldmatrix conflict-free).
// ---------------------------------------------------------------------------
#define QKV_PITCH 12
#define QKV_WS (128 * QKV_PITCH)
#define QKV_HS (256 * QKV_PITCH)

__global__ __launch_bounds__(256) void qkv_kernel(
    const float* __restrict__ hs,   // [8192, 1024]
    const float* __restrict__ w,    // [3072, 1024]
    const float* __restrict__ qb,
    const float* __restrict__ vb)
{
    __shared__ uint32_t Wsm[2 * QKV_WS];
    __shared__ uint32_t Hsm[2 * QKV_HS];
    const uint32_t WsmA = smem_u32(Wsm);
    const uint32_t HsmA = smem_u32(Hsm);

    const int tid  = threadIdx.x;
    const int lane = tid & 31;
    const int warp = tid >> 5;
    const int wo = (warp >> 2) * 64;
    const int wt = (warp & 3) * 64;
    const int o0 = blockIdx.x * 128;
    const int t0 = blockIdx.y * 256;
    const int r = lane >> 2;
    const int c = lane & 3;
    const int lt  = lane >> 3;    // ldmatrix tile index 0..3
    const int lr8 = lane & 7;     // row within tile

    float acc[4][8][4];
#pragma unroll
    for (int g = 0; g < 4; g++)
#pragma unroll
        for (int nj = 0; nj < 8; nj++)
#pragma unroll
            for (int q = 0; q < 4; q++) acc[g][nj][q] = 0.0f;

    float4 av[2], bv[4];
    auto fetch = [&](int k0) {
#pragma unroll
        for (int i = 0; i < 2; i++) {
            int slot = tid + 256 * i;
            int row = slot >> 2, f = slot & 3;
            av[i] = *(const float4*)&w[(size_t)(o0 + row) * HD + k0 + 4 * f];
        }
#pragma unroll
        for (int i = 0; i < 4; i++) {
            int slot = tid + 256 * i;
            int row = slot >> 2, f = slot & 3;
            bv[i] = *(const float4*)&hs[(size_t)(t0 + row) * HD + k0 + 4 * f];
        }
    };
    auto store = [&](int buf) {
#pragma unroll
        for (int i = 0; i < 2; i++) {
            int slot = tid + 256 * i;
            int row = slot >> 2, f = slot & 3;
            uint2 u; u.x = f2h2(av[i].x, av[i].y); u.y = f2h2(av[i].z, av[i].w);
            STS64V(WsmA + (buf * QKV_WS + row * QKV_PITCH + 2 * f) * 4, u);
        }
#pragma unroll
        for (int i = 0; i < 4; i++) {
            int slot = tid + 256 * i;
            int row = slot >> 2, f = slot & 3;
            uint2 u; u.x = f2h2(bv[i].x, bv[i].y); u.y = f2h2(bv[i].z, bv[i].w);
            STS64V(HsmA + (buf * QKV_HS + row * QKV_PITCH + 2 * f) * 4, u);
        }
    };

    fetch(0);
    store(0);
    __syncthreads();

    // ldmatrix row/col offsets (constant across chunks)
    const int arow = wo + (lt & 1) * 8 + lr8;      // + 16*g
    const int acol = (lt >> 1) * 4;
    const int brow = wt + (lt >> 1) * 8 + lr8;     // + 16*j
    const int bcol = (lt & 1) * 4;

    for (int kc = 0; kc < 64; kc++) {
        const int buf = kc & 1;
        if (kc < 63) fetch((kc + 1) * 16);

        const uint32_t WbA = WsmA + buf * QKV_WS * 4;
        const uint32_t HbA = HsmA + buf * QKV_HS * 4;
        uint32_t a[4][4], bbj[4][4];
#pragma unroll
        for (int g = 0; g < 4; g++)
            ldm4(a[g], WbA + ((arow + 16 * g) * QKV_PITCH + acol) * 4);
#pragma unroll
        for (int j = 0; j < 4; j++)
            ldm4(bbj[j], HbA + ((brow + 16 * j) * QKV_PITCH + bcol) * 4);
#pragma unroll
        for (int g = 0; g < 4; g++)
#pragma unroll
            for (int j = 0; j < 4; j++) {
                mma16(acc[g][2 * j],     a[g], &bbj[j][0]);
                mma16(acc[g][2 * j + 1], a[g], &bbj[j][2]);
            }

        if (kc < 63) {
            store(buf ^ 1);
            __syncthreads();
        }
    }

    // epilogue: seg uniform per CTA (o0 = bx*128; bx<8:Q, <16:K, else V)
    const int seg = o0 >> 10;
#pragma unroll
    for (int g = 0; g < 4; g++) {
#pragma unroll
        for (int rr = 0; rr < 2; rr++) {
            int o = o0 + wo + 16 * g + r + 8 * rr;
            int hd = o & 1023, h = hd >> 6, d = hd & 63;
            float qv = (seg == 0) ? qb[hd] : ((seg == 2) ? vb[hd] : 0.0f);
#pragma unroll
            for (int nj = 0; nj < 8; nj++) {
                int tok = t0 + wt + 8 * nj + 2 * c;
                int b_ = tok >> 10, n = tok & 1023;
                float v0 = acc[g][nj][2 * rr + 0];
                float v1 = acc[g][nj][2 * rr + 1];
                if (seg == 0) {
                    size_t idx = (((size_t)(b_ * H + h)) * N + n) * D + d;
                    g_Qh[idx]     = __float2half((v0 + qv) * 0.125f);
                    g_Qh[idx + D] = __float2half((v1 + qv) * 0.125f);
                } else if (seg == 1) {
                    size_t idx = (((size_t)(b_ * H + h)) * N + n) * D + d;
                    g_Kh[idx]     = __float2half(v0);
                    g_Kh[idx + D] = __float2half(v1);
                } else {
                    uint32_t* vp = (uint32_t*)g_Vt;
                    vp[(((size_t)(b_ * H + h)) * D + d) * (N / 2) + (n >> 1)] =
                        f2h2(v0 + qv, v1 + qv);
                }
            }
        }
    }
}

// ---------------------------------------------------------------------------
// Kernel 2: flash attention, fp16 m16n8k16 + ldmatrix. 128 q-rows/CTA, 8 warps.
// pitch 36 words (144B: stride/16=9 odd -> ldmatrix conflict-free).
// ---------------------------------------------------------------------------
#define AT_PITCH 36

__global__ __launch_bounds__(256) void attn_kernel(
    const int* __restrict__ mask,
    float*     __restrict__ out)
{
    __shared__ uint32_t Ks[64 * AT_PITCH];
    __shared__ uint32_t Vt[64 * AT_PITCH];
    __shared__ uint32_t Ps[128 * AT_PITCH];
    const uint32_t KsA = smem_u32(Ks);
    const uint32_t VtA = smem_u32(Vt);
    const uint32_t PsA = smem_u32(Ps);

    const int tid  = threadIdx.x;
    const int lane = tid & 31;
    const int warp = tid >> 5;
    const int q0 = blockIdx.x * 128;
    const int h  = blockIdx.y;
    const int b  = blockIdx.z;
    const int qw = warp * 16;
    const int r = lane >> 2;
    const int c = lane & 3;
    const int lt  = lane >> 3;
    const int lr8 = lane & 7;

    const __half* Qh  = g_Qh + (size_t)(b * H + h) * N * D;
    const __half* Kh  = g_Kh + (size_t)(b * H + h) * N * D;
    const __half* Vth = g_Vt + (size_t)(b * H + h) * D * N;
    const float*  rb  = g_RB + (size_t)h * N * N;
    const int*    mk  = mask + b * N;

    // ldmatrix lane geometry
    const int qrow = qw + (lt & 1) * 8 + lr8;      // A-frag rows (Q and P)
    const int qcol = (lt >> 1) * 4;
    const int krow = (lt >> 1) * 8 + lr8;          // B-frag rows (K and Vt), + 16*j
    const int kcol = (lt & 1) * 4;

    // stage this warp's 16 Q rows into Ps, then lift fragments
#pragma unroll
    for (int i = 0; i < 4; i++) {
        int slot = lane + 32 * i;
        int row16 = slot >> 3, j = slot & 7;
        uint4 v = ((const uint4*)(Qh + (size_t)(q0 + qw + row16) * D))[j];
        STS128V(PsA + ((qw + row16) * AT_PITCH + 4 * j) * 4, v);
    }
    __syncwarp();

    uint32_t qa[4][4];
#pragma unroll
    for (int ks = 0; ks < 4; ks++)
        ldm4(qa[ks], PsA + (qrow * AT_PITCH + 8 * ks + qcol) * 4);

    float m0v = -INFINITY, m1v = -INFINITY, l0 = 0.0f, l1 = 0.0f;
    float oacc[8][4];
#pragma unroll
    for (int nb = 0; nb < 8; nb++)
#pragma unroll
        for (int q = 0; q < 4; q++) oacc[nb][q] = 0.0f;

    for (int t = 0; t < 16; t++) {
        const int k0 = t * 64;
        __syncthreads();   // prior tile's Ks/Vt reads complete

        // load K tile [key][d] and V tile (pre-transposed [d][key])
#pragma unroll
        for (int i = 0; i < 2; i++) {
            int slot = tid + 256 * i;
            int row = slot >> 3, j = slot & 7;
            uint4 kv = ((const uint4*)(Kh + (size_t)(k0 + row) * D))[j];
            STS128V(KsA + (row * AT_PITCH + 4 * j) * 4, kv);
            uint4 vv = ((const uint4*)(Vth + (size_t)row * N + k0))[j];
            STS128V(VtA + (row * AT_PITCH + 4 * j) * 4, vv);
        }
        __syncthreads();

        // S = Q @ K^T
        float sacc[8][4];
#pragma unroll
        for (int nb = 0; nb < 8; nb++)
#pragma unroll
            for (int q = 0; q < 4; q++) sacc[nb][q] = 0.0f;

#pragma unroll
        for (int ks = 0; ks < 4; ks++) {
#pragma unroll
            for (int j = 0; j < 4; j++) {
                uint32_t kb[4];
                ldm4(kb, KsA + ((krow + 16 * j) * AT_PITCH + 8 * ks + kcol) * 4);
                mma16(sacc[2 * j],     qa[ks], &kb[0]);
                mma16(sacc[2 * j + 1], qa[ks], &kb[2]);
            }
        }

        // bias + mask + row max
        const int row0 = q0 + qw + r;
        float rmax0 = -INFINITY, rmax1 = -INFINITY;
#pragma unroll
        for (int nb = 0; nb < 8; nb++) {
            int col = k0 + 8 * nb + 2 * c;
            float2 bz0 = *(const float2*)&rb[(size_t)row0 * N + col];
            float2 bz1 = *(const float2*)&rb[(size_t)(row0 + 8) * N + col];
            int2 mm = *(const int2*)&mk[col];
            float s0 = sacc[nb][0] + bz0.x; if (mm.x) s0 = 1e-8f;
            float s1 = sacc[nb][1] + bz0.y; if (mm.y) s1 = 1e-8f;
            float s2 = sacc[nb][2] + bz1.x; if (mm.x) s2 = 1e-8f;
            float s3 = sacc[nb][3] + bz1.y; if (mm.y) s3 = 1e-8f;
            sacc[nb][0] = s0; sacc[nb][1] = s1; sacc[nb][2] = s2; sacc[nb][3] = s3;
            rmax0 = fmaxf(rmax0, fmaxf(s0, s1));
            rmax1 = fmaxf(rmax1, fmaxf(s2, s3));
        }
        rmax0 = fmaxf(rmax0, __shfl_xor_sync(0xffffffffu, rmax0, 1));
        rmax0 = fmaxf(rmax0, __shfl_xor_sync(0xffffffffu, rmax0, 2));
        rmax1 = fmaxf(rmax1, __shfl_xor_sync(0xffffffffu, rmax1, 1));
        rmax1 = fmaxf(rmax1, __shfl_xor_sync(0xffffffffu, rmax1, 2));

        float mn0 = fmaxf(m0v, rmax0), mn1 = fmaxf(m1v, rmax1);
        float sc0 = __expf(m0v - mn0), sc1 = __expf(m1v - mn1);
        m0v = mn0; m1v = mn1;

        float rs0 = 0.0f, rs1 = 0.0f;
#pragma unroll
        for (int nb = 0; nb < 8; nb++) {
            float p0 = __expf(sacc[nb][0] - mn0);
            float p1 = __expf(sacc[nb][1] - mn0);
            float p2 = __expf(sacc[nb][2] - mn1);
            float p3 = __expf(sacc[nb][3] - mn1);
            rs0 += p0 + p1;
            rs1 += p2 + p3;
            Ps[(qw + r) * AT_PITCH + 4 * nb + c]     = f2h2(p0, p1);
            Ps[(qw + r + 8) * AT_PITCH + 4 * nb + c] = f2h2(p2, p3);
        }
        rs0 += __shfl_xor_sync(0xffffffffu, rs0, 1);
        rs0 += __shfl_xor_sync(0xffffffffu, rs0, 2);
        rs1 += __shfl_xor_sync(0xffffffffu, rs1, 1);
        rs1 += __shfl_xor_sync(0xffffffffu, rs1, 2);
        l0 = l0 * sc0 + rs0;
        l1 = l1 * sc1 + rs1;
#pragma unroll
        for (int nb = 0; nb < 8; nb++) {
            oacc[nb][0] *= sc0; oacc[nb][1] *= sc0;
            oacc[nb][2] *= sc1; oacc[nb][3] *= sc1;
        }
        __syncwarp();     // P rows owned per-warp

        // O += P @ V
#pragma unroll
        for (int ks = 0; ks < 4; ks++) {
            uint32_t pa[4];
            ldm4(pa, PsA + (qrow * AT_PITCH + 8 * ks + qcol) * 4);
#pragma unroll
            for (int j = 0; j < 4; j++) {
                uint32_t vb_[4];
                ldm4(vb_, VtA + ((krow + 16 * j) * AT_PITCH + 8 * ks + kcol) * 4);
                mma16(oacc[2 * j],     pa, &vb_[0]);
                mma16(oacc[2 * j + 1], pa, &vb_[2]);
            }
        }
    }

    // finalize
    const float inv0 = 1.0f / l0, inv1 = 1.0f / l1;
    const int n0_ = q0 + qw + r;
#pragma unroll
    for (int nb = 0; nb < 8; nb++) {
        int d = 8 * nb + 2 * c;
        float2 v0; v0.x = oacc[nb][0] * inv0; v0.y = oacc[nb][1] * inv0;
        *(float2*)&out[((size_t)b * N + n0_) * HD + h * D + d] = v0;
        float2 v1; v1.x = oacc[nb][2] * inv1; v1.y = oacc[nb][3] * inv1;
        *(float2*)&out[((size_t)b * N + n0_ + 8) * HD + h * D + d] = v1;
    }
}

extern "C" void kernel_launch(void* const* d_in, const int* in_sizes, int n_in,
                              void* d_out, int out_size)
{
    (void)in_sizes; (void)n_in; (void)out_size;
    const float* hs   = (const float*)d_in[0];
    const float* w    = (const float*)d_in[1];
    const float* qb   = (const float*)d_in[2];
    const float* vb   = (const float*)d_in[3];
    const float* rel  = (const float*)d_in[4];
    const float* rel2 = (const float*)d_in[5];
    const int*   mask = (const int*)d_in[6];
    float* out = (float*)d_out;

    bias_kernel<<<(H * N * N) / (256 * 4), 256>>>(rel, rel2);

    dim3 g1(3 * HD / 128, (B * N) / 256);        // (24, 32)
    qkv_kernel<<<g1, 256>>>(hs, w, qb, vb);

    dim3 g2(N / 128, H, B);                      // (8, 16, 8)
    attn_kernel<<<g2, 256>>>(mask, out);
}